// round 12
// baseline (speedup 1.0000x reference)
#include <cuda_runtime.h>
#include <math.h>
#include <cstdint>

// ---------------------------------------------------------------------------
// FastConvLSTM, position-major block-sparse recurrence + FFMA2, R12:
//   h/c layout: [b][pos*128 + ch]  (pos = y*4+x, 16 positions, 128 channels)
//   pre_i(p) = enc @ Qi(p);  pre_f(p) = enc @ Qf(p) + sum_q h[q,0:32]@Wblk
//   pre_o(p) = sum_q h[q,32:80]@Wblk;  pre_g(p) = sum_q h[q,80:128]@Wblk
//   c = sig(pre_f)*c + sig(pre_i)*tanh(pre_g); h = sig(pre_o)*tanh(c)
// Step CTA: 64 batch rows; processes 4 positions {corner,center,edge,edge}
// (exactly 25 neighbor blocks each) -> 128 identical CTAs = one wave.
// Ping-pong SMEM stages, one __syncthreads per K-chunk.
// ---------------------------------------------------------------------------

#define BATCH 2048
#define TSTEPS 128
#define FEAT 84
#define BT (BATCH * TSTEPS)

typedef unsigned long long ull;

__device__ __align__(128) float g_W1[FEAT * 64];
__device__ __align__(128) float g_b1[64];
__device__ __align__(128) float g_S[1024 * 64];        // S[o][c]
__device__ __align__(128) float g_Q[64 * 4096];        // [k][j]; j = gate*2048 + pos*128 + co
__device__ __align__(128) float g_bias_if[4096];       // [gate*2048 + pos*128 + co]
__device__ __align__(128) float g_Wblk[9 * 128 * 128]; // [offset][ci][co]
__device__ __align__(128) float g_bias_o[2048];        // [pos*128 + co]
__device__ __align__(128) float g_bias_g[2048];
__device__ __align__(128) float g_enc[(size_t)BT * 64];
__device__ __align__(128) float g_h[2][(size_t)BATCH * 2048];
__device__ __align__(128) float g_c[(size_t)BATCH * 2048];
__device__ __align__(128) float g_hid[(size_t)BATCH * 128];

// position groups: {corner, center, edge, edge} -> 4+9+6+6 = 25 blocks each
__constant__ int c_grp[16] = {
    0, 5, 1, 2,
    3, 6, 4, 7,
    12, 9, 13, 8,
    15, 10, 14, 11
};

// ---------------- f32x2 helpers ----------------

__device__ __forceinline__ uint32_t smem_u32(const void* p) {
    uint32_t a;
    asm("{ .reg .u64 t; cvta.to.shared.u64 t, %1; cvt.u32.u64 %0, t; }" : "=r"(a) : "l"(p));
    return a;
}
__device__ __forceinline__ void lds_b2(ull& x, ull& y, uint32_t addr) {
    asm volatile("ld.shared.v2.u64 {%0,%1}, [%2];" : "=l"(x), "=l"(y) : "r"(addr));
}
__device__ __forceinline__ ull dup2(float b) {
    ull d; asm("mov.b64 %0, {%1,%1};" : "=l"(d) : "f"(b)); return d;
}
__device__ __forceinline__ void fma2(ull& d, ull a, ull b) {
    asm("fma.rn.f32x2 %0, %1, %2, %0;" : "+l"(d) : "l"(a), "l"(b));
}
__device__ __forceinline__ float xlo(ull v) { return __uint_as_float((uint32_t)v); }
__device__ __forceinline__ float xhi(ull v) { return __uint_as_float((uint32_t)(v >> 32)); }

// ---------------- weight prep kernels (cheap, run every launch) ----------------

__global__ void k_prep_w1(const float* __restrict__ cw, const float* __restrict__ cb,
                          const float* __restrict__ gam, const float* __restrict__ bet,
                          const float* __restrict__ mean, const float* __restrict__ var) {
    int i = blockIdx.x * blockDim.x + threadIdx.x;
    if (i >= FEAT * 64) return;
    int f = i / 64, c = i % 64;
    float s = gam[c] * rsqrtf(var[c] + 1e-5f);
    g_W1[f * 64 + c] = cw[c * (FEAT * 3) + f * 3 + 1] * s;   // center tap only
    if (f == 0) g_b1[c] = (cb[c] - mean[c]) * s + bet[c];
}

__global__ void k_S(const float* __restrict__ lin_w) {
    int idx = blockIdx.x * blockDim.x + threadIdx.x;
    if (idx >= 1024 * 64) return;
    int o = idx >> 6, c = idx & 63;
    float s = 0.f;
#pragma unroll
    for (int j = 0; j < 16; j++) s += lin_w[(size_t)o * 1024 + (c << 4) + j];
    g_S[idx] = s;
}

__global__ void k_buildQ(const float* __restrict__ cell_w, const float* __restrict__ cell_b,
                         const float* __restrict__ lin_b) {
    int idx = blockIdx.x * blockDim.x + threadIdx.x;
    if (idx >= 4096 * 64) return;
    int j = idx / 64, c = idx % 64;
    int gate = j / 2048;               // 0 = i, 1 = f(x part)
    int jj = j % 2048;
    int co = jj / 16, pos = jj % 16;
    int py = pos / 4, px = pos % 4;
    int wco = (gate == 0) ? co : 128 + co;
    int nci = (gate == 0) ? 48 : 16;
    float acc = 0.f, bacc = 0.f;
    for (int ci = 0; ci < nci; ci++) {
        int xch = (gate == 0) ? ci : 48 + ci;
        for (int ky = 0; ky < 3; ky++) {
            int qy = py + ky - 1; if (qy < 0 || qy > 3) continue;
            for (int kx = 0; kx < 3; kx++) {
                int qx = px + kx - 1; if (qx < 0 || qx > 3) continue;
                float w = cell_w[(size_t)wco * 432 + ci * 9 + ky * 3 + kx];
                int o = xch * 16 + qy * 4 + qx;
                acc += w * g_S[o * 64 + c];
                if (c == 0) bacc += w * lin_b[o];
            }
        }
    }
    int newj = gate * 2048 + pos * 128 + co;
    g_Q[(size_t)c * 4096 + newj] = acc;
    if (c == 0) g_bias_if[newj] = cell_b[wco] + bacc;
}

__global__ void k_buildWblk(const float* __restrict__ cell_w) {
    int idx = blockIdx.x * blockDim.x + threadIdx.x;
    if (idx >= 9 * 128 * 128) return;
    int co = idx & 127;
    int ci = (idx >> 7) & 127;
    int di = idx >> 14;
    int ky = di / 3, kx = di % 3;
    int wco, ig;
    if (ci < 32)      { wco = 128 + co; ig = 16 + ci; }   // gate f: h ch 0..31
    else if (ci < 80) { wco = 256 + co; ig = ci - 32; }   // gate o: h ch 32..79
    else              { wco = 384 + co; ig = ci - 80; }   // gate g: h ch 80..127
    g_Wblk[idx] = cell_w[(size_t)wco * 432 + ig * 9 + ky * 3 + kx];
}

__global__ void k_bias_og(const float* __restrict__ cell_b) {
    int idx = blockIdx.x * blockDim.x + threadIdx.x;
    if (idx >= 2048) return;
    int co = idx & 127;
    g_bias_o[idx] = cell_b[256 + co];
    g_bias_g[idx] = cell_b[384 + co];
}

// ---------------- encoder ----------------

__global__ void k_enc(const float* __restrict__ x) {
    __shared__ float sW[FEAT * 64];
    __shared__ float sb[64];
    __shared__ float sx[32][FEAT];
    int tid = threadIdx.x;
    for (int i = tid; i < FEAT * 64; i += 256) sW[i] = g_W1[i];
    if (tid < 64) sb[tid] = g_b1[tid];
    size_t row0 = (size_t)blockIdx.x * 32;
    for (int i = tid; i < 32 * FEAT; i += 256) {
        int r = i / FEAT, f = i % FEAT;
        sx[r][f] = x[(row0 + r) * FEAT + f];
    }
    __syncthreads();
    int c = tid & 63;
    int rg = tid >> 6;
    for (int rr = 0; rr < 8; rr++) {
        int r = rg * 8 + rr;
        float acc = sb[c];
#pragma unroll 4
        for (int f = 0; f < FEAT; f++) acc += sx[r][f] * sW[f * 64 + c];
        g_enc[(row0 + r) * 64 + c] = fmaxf(acc, 0.f);
    }
}

__global__ void k_zero() {
    size_t i = (size_t)blockIdx.x * blockDim.x + threadIdx.x;
    if (i < (size_t)BATCH * 2048) { g_h[0][i] = 0.f; g_c[i] = 0.f; }
}

// ---------------- recurrent step ----------------
// CTA: 64 batch rows x 128 channels, 4 positions sequentially.
// Thread (tx,ty): rows 4ty..4ty+3, cols {4tx..+3, 64+4tx..+3}.

#define INNERB(ACC, ST, BADDR)                                                      \
    do {                                                                            \
        _Pragma("unroll 4")                                                         \
        for (int k = 0; k < 16; k++) {                                              \
            float4 a = *(const float4*)&us[ST][k][ty << 2];                         \
            ull A0 = dup2(a.x), A1 = dup2(a.y), A2 = dup2(a.z), A3 = dup2(a.w);     \
            ull b0, b1, b2, b3;                                                     \
            lds_b2(b0, b1, (BADDR) + k * 512);                                      \
            lds_b2(b2, b3, (BADDR) + k * 512 + 256);                                \
            fma2(ACC[0], A0, b0);  fma2(ACC[1], A0, b1);                            \
            fma2(ACC[2], A0, b2);  fma2(ACC[3], A0, b3);                            \
            fma2(ACC[4], A1, b0);  fma2(ACC[5], A1, b1);                            \
            fma2(ACC[6], A1, b2);  fma2(ACC[7], A1, b3);                            \
            fma2(ACC[8], A2, b0);  fma2(ACC[9], A2, b1);                            \
            fma2(ACC[10], A2, b2); fma2(ACC[11], A2, b3);                           \
            fma2(ACC[12], A3, b0); fma2(ACC[13], A3, b1);                           \
            fma2(ACC[14], A3, b2); fma2(ACC[15], A3, b3);                           \
        }                                                                           \
    } while (0)

__global__ void __launch_bounds__(256, 1) k_step(int t) {
    __shared__ float us[2][16][64];     // [stage][k][b]
    __shared__ float ws[2][16][128];    // [stage][k][co]
    __shared__ float ws2[2][16][128];   // [stage][k][co] (enc dual B)
    const int tid = threadIdx.x;
    const int tx = tid & 15, ty = tid >> 4;
    const int bb = blockIdx.x << 6;
    const float* __restrict__ hin = g_h[t & 1];
    float* __restrict__ hout = g_h[(t & 1) ^ 1];
    const float* enc_t = g_enc + ((size_t)bb * TSTEPS + t) * 64;
    const float* hrow = hin + (size_t)bb * 2048;
    const uint32_t ws_b = smem_u32(ws), ws2_b = smem_u32(ws2);
    const int lb = tid >> 2, lk4 = (tid & 3) << 2;   // A loader: row lb, k sub lk4
    const int wk = tid >> 4, wj8 = (tid & 15) << 3;  // B loader: k row wk, col wj8

#pragma unroll 1
    for (int pi = 0; pi < 4; pi++) {
        const int p = c_grp[blockIdx.y * 4 + pi];
        const int py = p >> 2, px = p & 3;

        // neighbor list (uniform per CTA)
        int nq[9], nd[9], nn = 0;
#pragma unroll
        for (int di = 0; di < 9; di++) {
            int qy = py + di / 3 - 1, qx = px + di % 3 - 1;
            if ((unsigned)qy < 4u && (unsigned)qx < 4u) { nq[nn] = qy * 4 + qx; nd[nn] = di; nn++; }
        }
        const int NC = 4 + 8 * nn;

        ull acc_i[16], acc_f[16], acc_o[16], acc_g[16];
#pragma unroll
        for (int e = 0; e < 16; e++) { acc_i[e] = 0ull; acc_f[e] = 0ull; acc_o[e] = 0ull; acc_g[e] = 0ull; }

        float4 av, b1a, b1b, b2a, b2b;
        auto loadc = [&](int ci) {
            if (ci < 4) {
                const float* Ap = enc_t + (size_t)lb * (TSTEPS * 64) + ci * 16 + lk4;
                av = *(const float4*)Ap;
                const float* B1 = g_Q + (size_t)(ci * 16 + wk) * 4096 + p * 128 + wj8;
                b1a = *(const float4*)B1;
                b1b = *(const float4*)(B1 + 4);
                const float* B2 = B1 + 2048;
                b2a = *(const float4*)B2;
                b2b = *(const float4*)(B2 + 4);
            } else {
                int n = (ci - 4) >> 3, kt = (ci - 4) & 7;
                const float* Ap = hrow + nq[n] * 128 + (size_t)lb * 2048 + kt * 16 + lk4;
                av = *(const float4*)Ap;
                const float* Bp = g_Wblk + (size_t)nd[n] * 16384 + (size_t)(kt * 16 + wk) * 128 + wj8;
                b1a = *(const float4*)Bp;
                b1b = *(const float4*)(Bp + 4);
            }
        };
        auto stsc = [&](int ci, int st) {
            us[st][lk4 + 0][lb] = av.x; us[st][lk4 + 1][lb] = av.y;
            us[st][lk4 + 2][lb] = av.z; us[st][lk4 + 3][lb] = av.w;
            *(float4*)&ws[st][wk][wj8] = b1a; *(float4*)&ws[st][wk][wj8 + 4] = b1b;
            if (ci < 4) {
                *(float4*)&ws2[st][wk][wj8] = b2a; *(float4*)&ws2[st][wk][wj8 + 4] = b2b;
            }
        };

        __syncthreads();            // prior position's readers done before stage0 reuse
        loadc(0);
        stsc(0, 0);
        __syncthreads();

#pragma unroll 1
        for (int ci = 0; ci < NC; ci++) {
            const int st = ci & 1;
            if (ci + 1 < NC) loadc(ci + 1);
            const uint32_t ba = ws_b + st * 8192 + tx * 16;
            if (ci < 4) {
                INNERB(acc_i, st, ba);
                const uint32_t ba2 = ws2_b + st * 8192 + tx * 16;
                INNERB(acc_f, st, ba2);
            } else {
                int kt = (ci - 4) & 7;
                if (kt < 2)      { INNERB(acc_f, st, ba); }
                else if (kt < 5) { INNERB(acc_o, st, ba); }
                else             { INNERB(acc_g, st, ba); }
            }
            if (ci + 1 < NC) stsc(ci + 1, st ^ 1);
            __syncthreads();
        }

        // ===== fused LSTM epilogue for position p =====
#pragma unroll
        for (int m = 0; m < 4; m++) {
            int b = bb + (ty << 2) + m;
            size_t roff = (size_t)b * 2048 + p * 128;
#pragma unroll
            for (int g2 = 0; g2 < 2; g2++) {
                int colbase = g2 * 64 + (tx << 2);
                size_t off = roff + colbase;
                float4 cold = *(const float4*)(g_c + off);
                float cold4[4] = {cold.x, cold.y, cold.z, cold.w};
                float cn[4], hn[4];
#pragma unroll
                for (int e2 = 0; e2 < 4; e2++) {
                    int jp = g2 * 2 + (e2 >> 1);
                    int e = m * 4 + jp;
                    bool hi = e2 & 1;
                    int jn = p * 128 + colbase + e2;
                    float pi2 = (hi ? xhi(acc_i[e]) : xlo(acc_i[e])) + g_bias_if[jn];
                    float pf = (hi ? xhi(acc_f[e]) : xlo(acc_f[e])) + g_bias_if[2048 + jn];
                    float po = (hi ? xhi(acc_o[e]) : xlo(acc_o[e])) + g_bias_o[jn];
                    float pg = (hi ? xhi(acc_g[e]) : xlo(acc_g[e])) + g_bias_g[jn];
                    float si = 1.f / (1.f + __expf(-pi2));
                    float sf = 1.f / (1.f + __expf(-pf));
                    float so = 1.f / (1.f + __expf(-po));
                    float tg = 2.f / (1.f + __expf(-2.f * pg)) - 1.f;
                    float c2 = sf * cold4[e2] + si * tg;
                    cn[e2] = c2;
                    float tc = 2.f / (1.f + __expf(-2.f * c2)) - 1.f;
                    hn[e2] = so * tc;
                }
                *(float4*)(g_c + off)  = make_float4(cn[0], cn[1], cn[2], cn[3]);
                *(float4*)(hout + off) = make_float4(hn[0], hn[1], hn[2], hn[3]);
            }
        }
    }
}

// ---------------- classifier ----------------
// h columns are position-major (pos*128+co); original feature index = co*16+pos.

__global__ void k_cls1(const float* __restrict__ w, const float* __restrict__ bias) {
    __shared__ float sf[16][64];
    __shared__ float sw[64][129];
    const float* hptr = g_h[0];
    int tid = threadIdx.x;
    int b0 = blockIdx.x * 16;
    float acc[16];
#pragma unroll
    for (int r = 0; r < 16; r++) acc[r] = 0.f;
    for (int k0 = 0; k0 < 2048; k0 += 64) {
        __syncthreads();
        for (int i = tid; i < 16 * 64; i += 128) {
            int r = i / 64, kl = i % 64;
            sf[r][kl] = hptr[(size_t)(b0 + r) * 2048 + k0 + kl];
        }
        {
            int kl = tid % 64, og = tid / 64;
            int kg = k0 + kl;
            int worig = (kg & 127) * 16 + (kg >> 7);   // pos-major -> channel-major
            for (int o = og; o < 128; o += 2)
                sw[kl][o] = w[(size_t)o * 2048 + worig];
        }
        __syncthreads();
        for (int kl = 0; kl < 64; kl++) {
            float wv = sw[kl][tid];
#pragma unroll
            for (int r = 0; r < 16; r++) acc[r] += sf[r][kl] * wv;
        }
    }
    for (int r = 0; r < 16; r++)
        g_hid[(size_t)(b0 + r) * 128 + tid] = fmaxf(acc[r] + bias[tid], 0.f);
}

__global__ void k_cls2(const float* __restrict__ w, const float* __restrict__ b,
                       float* __restrict__ out) {
    int bi = blockIdx.x * blockDim.x + threadIdx.x;
    if (bi >= BATCH) return;
    float a0 = b[0], a1 = b[1];
    for (int k = 0; k < 128; k++) {
        float h = g_hid[(size_t)bi * 128 + k];
        a0 += h * w[k];
        a1 += h * w[128 + k];
    }
    out[bi * 2 + 0] = a0;
    out[bi * 2 + 1] = a1;
}

// ---------------- launch ----------------

extern "C" void kernel_launch(void* const* d_in, const int* in_sizes, int n_in,
                              void* d_out, int out_size) {
    const float* x        = (const float*)d_in[0];
    const float* conv1d_w = (const float*)d_in[1];
    const float* conv1d_b = (const float*)d_in[2];
    const float* bn_gamma = (const float*)d_in[3];
    const float* bn_beta  = (const float*)d_in[4];
    const float* bn_mean  = (const float*)d_in[5];
    const float* bn_var   = (const float*)d_in[6];
    const float* lin_w    = (const float*)d_in[7];
    const float* lin_b    = (const float*)d_in[8];
    const float* cell_w   = (const float*)d_in[9];
    const float* cell_b   = (const float*)d_in[10];
    const float* cls1_w   = (const float*)d_in[11];
    const float* cls1_b   = (const float*)d_in[12];
    const float* cls2_w   = (const float*)d_in[13];
    const float* cls2_b   = (const float*)d_in[14];
    float* out = (float*)d_out;

    k_prep_w1<<<(FEAT * 64 + 255) / 256, 256>>>(conv1d_w, conv1d_b, bn_gamma, bn_beta, bn_mean, bn_var);
    k_S<<<(1024 * 64 + 255) / 256, 256>>>(lin_w);
    k_buildQ<<<(4096 * 64 + 255) / 256, 256>>>(cell_w, cell_b, lin_b);
    k_buildWblk<<<(9 * 128 * 128 + 255) / 256, 256>>>(cell_w);
    k_bias_og<<<(2048 + 255) / 256, 256>>>(cell_b);
    k_enc<<<BT / 32, 256>>>(x);
    k_zero<<<(int)(((size_t)BATCH * 2048 + 255) / 256), 256>>>();

    for (int t = 0; t < TSTEPS; t++)
        k_step<<<dim3(BATCH / 64, 4), 256>>>(t);

    k_cls1<<<BATCH / 16, 128>>>(cls1_w, cls1_b);
    k_cls2<<<(BATCH + 127) / 128, 128>>>(cls2_w, cls2_b, out);
}

// round 13
// speedup vs baseline: 2.1124x; 2.1124x over previous
#include <cuda_runtime.h>
#include <math.h>
#include <cstdint>

// ---------------------------------------------------------------------------
// FastConvLSTM, position-major block-sparse recurrence on tf32 mma.sync:
//   h/c layout: [b][pos*128 + ch]
//   pre_i(p) = enc @ Qi(p);  pre_f(p) = enc @ Qf(p) + sum_q h[q,0:32]@W
//   pre_o(p) = sum_q h[q,32:80]@W;  pre_g(p) = sum_q h[q,80:128]@W
//   c = sig(pre_f)*c + sig(pre_i)*tanh(pre_g); h = sig(pre_o)*tanh(c)
// Step CTA: 64 batch x 128 ch at one position. 8 warps (2m x 4n), warp tile
// 32x32, mma.sync.m16n8k8 tf32. B weights preformatted fragment-canonical in
// gmem (L2-resident), LDG.64 direct to registers, double buffered.
// A staged through ping-pong smem us[64][20] (conflict-free fragment LDS).
// ---------------------------------------------------------------------------

#define BATCH 2048
#define TSTEPS 128
#define FEAT 84
#define BT (BATCH * TSTEPS)

__device__ __align__(128) float g_W1[FEAT * 64];
__device__ __align__(128) float g_b1[64];
__device__ __align__(128) float g_S[1024 * 64];        // S[o][c]
__device__ __align__(128) float g_QF[2 * 16 * 4 * 2048];   // frag-canonical Qi/Qf
__device__ __align__(128) float g_WF[9 * 8 * 2048];        // frag-canonical Wblk
__device__ __align__(128) float g_bias_if[4096];       // [gate*2048 + pos*128 + co]
__device__ __align__(128) float g_bias_o[2048];        // [pos*128 + co]
__device__ __align__(128) float g_bias_g[2048];
__device__ __align__(128) float g_enc[(size_t)BT * 64];
__device__ __align__(128) float g_h[2][(size_t)BATCH * 2048];
__device__ __align__(128) float g_c[(size_t)BATCH * 2048];
__device__ __align__(128) float g_hid[(size_t)BATCH * 128];

// ---------------- helpers ----------------

__device__ __forceinline__ float to_tf32(float x) {
    uint32_t u; asm("cvt.rna.tf32.f32 %0, %1;" : "=r"(u) : "f"(x));
    return __uint_as_float(u);
}
__device__ __forceinline__ void mma_tf32(float* d, const uint32_t* a, const uint32_t* b) {
    asm volatile(
        "mma.sync.aligned.m16n8k8.row.col.f32.tf32.tf32.f32 "
        "{%0,%1,%2,%3}, {%4,%5,%6,%7}, {%8,%9}, {%0,%1,%2,%3};\n"
        : "+f"(d[0]), "+f"(d[1]), "+f"(d[2]), "+f"(d[3])
        : "r"(a[0]), "r"(a[1]), "r"(a[2]), "r"(a[3]), "r"(b[0]), "r"(b[1]));
}

// ---------------- weight prep kernels ----------------

__global__ void k_prep_w1(const float* __restrict__ cw, const float* __restrict__ cb,
                          const float* __restrict__ gam, const float* __restrict__ bet,
                          const float* __restrict__ mean, const float* __restrict__ var) {
    int i = blockIdx.x * blockDim.x + threadIdx.x;
    if (i >= FEAT * 64) return;
    int f = i / 64, c = i % 64;
    float s = gam[c] * rsqrtf(var[c] + 1e-5f);
    g_W1[f * 64 + c] = cw[c * (FEAT * 3) + f * 3 + 1] * s;   // center tap only
    if (f == 0) g_b1[c] = (cb[c] - mean[c]) * s + bet[c];
}

__global__ void k_S(const float* __restrict__ lin_w) {
    int idx = blockIdx.x * blockDim.x + threadIdx.x;
    if (idx >= 1024 * 64) return;
    int o = idx >> 6, c = idx & 63;
    float s = 0.f;
#pragma unroll
    for (int j = 0; j < 16; j++) s += lin_w[(size_t)o * 1024 + (c << 4) + j];
    g_S[idx] = s;
}

// Q in fragment-canonical order:
// idx = ((((gate*16+p)*4+kc)*2+kk)*16+nt)*64 + lane*2 + e
// value = Q[c = kc*16+kk*8+tig+4e][co = nt*8+gid]  (tf32-rounded)
__global__ void k_buildQF(const float* __restrict__ cell_w) {
    int idx = blockIdx.x * blockDim.x + threadIdx.x;
    if (idx >= 2 * 16 * 4 * 2048) return;
    int e = idx & 1;
    int lane = (idx >> 1) & 31;
    int nt = (idx >> 6) & 15;
    int kk = (idx >> 10) & 1;
    int kc = (idx >> 11) & 3;
    int p = (idx >> 13) & 15;
    int gate = idx >> 17;
    int gid = lane >> 2, tig = lane & 3;
    int c = kc * 16 + kk * 8 + tig + e * 4;
    int co = nt * 8 + gid;
    int py = p >> 2, px = p & 3;
    int wco = (gate == 0) ? co : 128 + co;
    int nci = (gate == 0) ? 48 : 16;
    float acc = 0.f;
    for (int ci = 0; ci < nci; ci++) {
        int xch = (gate == 0) ? ci : 48 + ci;
        for (int ky = 0; ky < 3; ky++) {
            int qy = py + ky - 1; if (qy < 0 || qy > 3) continue;
            for (int kx = 0; kx < 3; kx++) {
                int qx = px + kx - 1; if (qx < 0 || qx > 3) continue;
                float w = cell_w[(size_t)wco * 432 + ci * 9 + ky * 3 + kx];
                acc += w * g_S[(xch * 16 + qy * 4 + qx) * 64 + c];
            }
        }
    }
    g_QF[idx] = to_tf32(acc);
}

__global__ void k_biasIF(const float* __restrict__ cell_w, const float* __restrict__ cell_b,
                         const float* __restrict__ lin_b) {
    int idx = blockIdx.x * blockDim.x + threadIdx.x;
    if (idx >= 4096) return;
    int gate = idx >> 11;
    int p = (idx >> 7) & 15;
    int co = idx & 127;
    int py = p >> 2, px = p & 3;
    int wco = (gate == 0) ? co : 128 + co;
    int nci = (gate == 0) ? 48 : 16;
    float bacc = 0.f;
    for (int ci = 0; ci < nci; ci++) {
        int xch = (gate == 0) ? ci : 48 + ci;
        for (int ky = 0; ky < 3; ky++) {
            int qy = py + ky - 1; if (qy < 0 || qy > 3) continue;
            for (int kx = 0; kx < 3; kx++) {
                int qx = px + kx - 1; if (qx < 0 || qx > 3) continue;
                float w = cell_w[(size_t)wco * 432 + ci * 9 + ky * 3 + kx];
                bacc += w * lin_b[xch * 16 + qy * 4 + qx];
            }
        }
    }
    g_bias_if[idx] = cell_b[wco] + bacc;
}

// Wblk in fragment-canonical order:
// idx = ((((di*8+kc)*2+kk)*16+nt)*64 + lane*2 + e
// value = W[ci = kc*16+kk*8+tig+4e][co = nt*8+gid]
__global__ void k_buildWF(const float* __restrict__ cell_w) {
    int idx = blockIdx.x * blockDim.x + threadIdx.x;
    if (idx >= 9 * 8 * 2048) return;
    int e = idx & 1;
    int lane = (idx >> 1) & 31;
    int nt = (idx >> 6) & 15;
    int kk = (idx >> 10) & 1;
    int kc = (idx >> 11) & 7;
    int di = idx >> 14;
    int gid = lane >> 2, tig = lane & 3;
    int ci = kc * 16 + kk * 8 + tig + e * 4;
    int co = nt * 8 + gid;
    int ky = di / 3, kx = di % 3;
    int wco, ig;
    if (ci < 32)      { wco = 128 + co; ig = 16 + ci; }   // gate f: h ch 0..31
    else if (ci < 80) { wco = 256 + co; ig = ci - 32; }   // gate o
    else              { wco = 384 + co; ig = ci - 80; }   // gate g
    g_WF[idx] = to_tf32(cell_w[(size_t)wco * 432 + ig * 9 + ky * 3 + kx]);
}

__global__ void k_bias_og(const float* __restrict__ cell_b) {
    int idx = blockIdx.x * blockDim.x + threadIdx.x;
    if (idx >= 2048) return;
    int co = idx & 127;
    g_bias_o[idx] = cell_b[256 + co];
    g_bias_g[idx] = cell_b[384 + co];
}

// ---------------- encoder (tf32-rounded output) ----------------

__global__ void k_enc(const float* __restrict__ x) {
    __shared__ float sW[FEAT * 64];
    __shared__ float sb[64];
    __shared__ float sx[32][FEAT];
    int tid = threadIdx.x;
    for (int i = tid; i < FEAT * 64; i += 256) sW[i] = g_W1[i];
    if (tid < 64) sb[tid] = g_b1[tid];
    size_t row0 = (size_t)blockIdx.x * 32;
    for (int i = tid; i < 32 * FEAT; i += 256) {
        int r = i / FEAT, f = i % FEAT;
        sx[r][f] = x[(row0 + r) * FEAT + f];
    }
    __syncthreads();
    int c = tid & 63;
    int rg = tid >> 6;
    for (int rr = 0; rr < 8; rr++) {
        int r = rg * 8 + rr;
        float acc = sb[c];
#pragma unroll 4
        for (int f = 0; f < FEAT; f++) acc += sx[r][f] * sW[f * 64 + c];
        g_enc[(row0 + r) * 64 + c] = to_tf32(fmaxf(acc, 0.f));
    }
}

__global__ void k_zero() {
    size_t i = (size_t)blockIdx.x * blockDim.x + threadIdx.x;
    if (i < (size_t)BATCH * 2048) { g_h[0][i] = 0.f; g_c[i] = 0.f; }
}

// ---------------- recurrent step: tf32 mma.sync ----------------

#define LDB(DST, BASE)                                                          \
    do {                                                                        \
        _Pragma("unroll")                                                       \
        for (int kk_ = 0; kk_ < 2; kk_++)                                       \
            _Pragma("unroll")                                                   \
            for (int nt_ = 0; nt_ < 4; nt_++)                                   \
                DST[kk_][nt_] = *(const float2*)((BASE) +                       \
                    ((kk_ * 16 + nt0 + nt_) * 64 + lane * 2));                  \
    } while (0)

#define CPB(DST, SRC)                                                           \
    do {                                                                        \
        _Pragma("unroll")                                                       \
        for (int kk_ = 0; kk_ < 2; kk_++)                                       \
            _Pragma("unroll")                                                   \
            for (int nt_ = 0; nt_ < 4; nt_++) DST[kk_][nt_] = SRC[kk_][nt_];    \
    } while (0)

#define DO_CHUNK(ACC, BARR, ST)                                                 \
    do {                                                                        \
        _Pragma("unroll")                                                       \
        for (int kk_ = 0; kk_ < 2; kk_++) {                                     \
            uint32_t af_[2][4];                                                 \
            _Pragma("unroll")                                                   \
            for (int mt_ = 0; mt_ < 2; mt_++) {                                 \
                int r0_ = m0 + mt_ * 16 + gid;                                  \
                af_[mt_][0] = __float_as_uint(us[ST][r0_][kk_ * 8 + tig]);      \
                af_[mt_][1] = __float_as_uint(us[ST][r0_ + 8][kk_ * 8 + tig]);  \
                af_[mt_][2] = __float_as_uint(us[ST][r0_][kk_ * 8 + tig + 4]);  \
                af_[mt_][3] = __float_as_uint(us[ST][r0_ + 8][kk_ * 8 + tig + 4]); \
            }                                                                   \
            _Pragma("unroll")                                                   \
            for (int nt_ = 0; nt_ < 4; nt_++) {                                 \
                uint32_t bf_[2] = {__float_as_uint(BARR[kk_][nt_].x),           \
                                   __float_as_uint(BARR[kk_][nt_].y)};          \
                mma_tf32(&ACC[(0 * 4 + nt_) * 4], af_[0], bf_);                 \
                mma_tf32(&ACC[(1 * 4 + nt_) * 4], af_[1], bf_);                 \
            }                                                                   \
        }                                                                       \
    } while (0)

__global__ void __launch_bounds__(256, 1) k_step(int t) {
    __shared__ __align__(16) float us[2][64][20];
    const int tid = threadIdx.x;
    const int lane = tid & 31, wid = tid >> 5;
    const int gid = lane >> 2, tig = lane & 3;
    const int warp_m = wid & 1, warp_n = wid >> 1;
    const int m0 = warp_m * 32;
    const int nt0 = warp_n * 4;               // n-tile base (n0 = nt0*8)
    const int lb = tid >> 2, lk4 = (tid & 3) << 2;
    const int bb = blockIdx.x << 6;
    const int p = blockIdx.y;
    const int py = p >> 2, px = p & 3;
    const float* __restrict__ hin = g_h[t & 1];
    float* __restrict__ hout = g_h[(t & 1) ^ 1];
    const float* enc_t = g_enc + ((size_t)bb * TSTEPS + t) * 64;
    const float* hrow = hin + (size_t)bb * 2048;

    float acc_i[32], acc_f[32];
#pragma unroll
    for (int e = 0; e < 32; e++) { acc_i[e] = 0.f; acc_f[e] = 0.f; }

    // ===== enc phase: 4 dual chunks (gate i + gate f x-part) =====
    {
        const float* qI = g_QF + (size_t)(0 * 16 + p) * 8192;
        const float* qF = g_QF + (size_t)(1 * 16 + p) * 8192;
        float2 bc[2][4], bc2[2][4], bn[2][4], bn2[2][4];
        float4 av = *(const float4*)(enc_t + (size_t)lb * (TSTEPS * 64) + lk4);
        LDB(bc, qI);
        LDB(bc2, qF);
        *(float4*)&us[0][lb][lk4] = av;
        __syncthreads();
#pragma unroll 1
        for (int kc = 0; kc < 4; kc++) {
            const int st = kc & 1;
            if (kc < 3) {
                av = *(const float4*)(enc_t + (size_t)lb * (TSTEPS * 64) + (kc + 1) * 16 + lk4);
                LDB(bn, qI + (kc + 1) * 2048);
                LDB(bn2, qF + (kc + 1) * 2048);
            }
            DO_CHUNK(acc_i, bc, st);
            DO_CHUNK(acc_f, bc2, st);
            if (kc < 3) {
                *(float4*)&us[st ^ 1][lb][lk4] = av;
                CPB(bc, bn);
                CPB(bc2, bn2);
            }
            __syncthreads();
        }
    }

    // ===== h phase: neighbor blocks, k16 chunks =====
    float acc_o[32], acc_g[32];
#pragma unroll
    for (int e = 0; e < 32; e++) { acc_o[e] = 0.f; acc_g[e] = 0.f; }
    {
        int nq[9], nd[9], nn = 0;
#pragma unroll
        for (int di = 0; di < 9; di++) {
            int qy = py + di / 3 - 1, qx = px + di % 3 - 1;
            if ((unsigned)qy < 4u && (unsigned)qx < 4u) { nq[nn] = qy * 4 + qx; nd[nn] = di; nn++; }
        }
        const int NH = nn * 8;
        float2 bc[2][4], bn[2][4];
        float4 av = *(const float4*)(hrow + nq[0] * 128 + (size_t)lb * 2048 + lk4);
        LDB(bc, g_WF + (size_t)nd[0] * 16384);
        *(float4*)&us[0][lb][lk4] = av;
        __syncthreads();
#pragma unroll 1
        for (int ci = 0; ci < NH; ci++) {
            const int st = ci & 1;
            if (ci + 1 < NH) {
                int n2 = (ci + 1) >> 3, kt2 = (ci + 1) & 7;
                av = *(const float4*)(hrow + nq[n2] * 128 + (size_t)lb * 2048 + kt2 * 16 + lk4);
                LDB(bn, g_WF + (size_t)nd[n2] * 16384 + kt2 * 2048);
            }
            const int kt = ci & 7;
            if (kt < 2)      { DO_CHUNK(acc_f, bc, st); }
            else if (kt < 5) { DO_CHUNK(acc_o, bc, st); }
            else             { DO_CHUNK(acc_g, bc, st); }
            if (ci + 1 < NH) {
                *(float4*)&us[st ^ 1][lb][lk4] = av;
                CPB(bc, bn);
            }
            __syncthreads();
        }
    }

    // ===== fused LSTM epilogue =====
#pragma unroll
    for (int mt = 0; mt < 2; mt++) {
#pragma unroll
        for (int rh = 0; rh < 2; rh++) {
            int row = bb + m0 + mt * 16 + gid + rh * 8;
            size_t roff = (size_t)row * 2048 + p * 128;
#pragma unroll
            for (int nt = 0; nt < 4; nt++) {
                int col = (nt0 + nt) * 8 + tig * 2;
                size_t off = roff + col;
                int jn = p * 128 + col;
                float2 cold = *(const float2*)(g_c + off);
                float cold2[2] = {cold.x, cold.y};
                float cn[2], hn[2];
#pragma unroll
                for (int e = 0; e < 2; e++) {
                    int ai = (mt * 4 + nt) * 4 + rh * 2 + e;
                    float pi2 = acc_i[ai] + g_bias_if[jn + e];
                    float pf = acc_f[ai] + g_bias_if[2048 + jn + e];
                    float po = acc_o[ai] + g_bias_o[jn + e];
                    float pg = acc_g[ai] + g_bias_g[jn + e];
                    float si = 1.f / (1.f + __expf(-pi2));
                    float sf = 1.f / (1.f + __expf(-pf));
                    float so = 1.f / (1.f + __expf(-po));
                    float tg = 2.f / (1.f + __expf(-2.f * pg)) - 1.f;
                    float c2 = sf * cold2[e] + si * tg;
                    cn[e] = c2;
                    float tc = 2.f / (1.f + __expf(-2.f * c2)) - 1.f;
                    hn[e] = to_tf32(so * tc);
                }
                *(float2*)(g_c + off)  = make_float2(cn[0], cn[1]);
                *(float2*)(hout + off) = make_float2(hn[0], hn[1]);
            }
        }
    }
}

// ---------------- classifier ----------------
// h columns are position-major (pos*128+co); original feature index = co*16+pos.

__global__ void k_cls1(const float* __restrict__ w, const float* __restrict__ bias) {
    __shared__ float sf[16][64];
    __shared__ float sw[64][129];
    const float* hptr = g_h[0];
    int tid = threadIdx.x;
    int b0 = blockIdx.x * 16;
    float acc[16];
#pragma unroll
    for (int r = 0; r < 16; r++) acc[r] = 0.f;
    for (int k0 = 0; k0 < 2048; k0 += 64) {
        __syncthreads();
        for (int i = tid; i < 16 * 64; i += 128) {
            int r = i / 64, kl = i % 64;
            sf[r][kl] = hptr[(size_t)(b0 + r) * 2048 + k0 + kl];
        }
        {
            int kl = tid % 64, og = tid / 64;
            int kg = k0 + kl;
            int worig = (kg & 127) * 16 + (kg >> 7);   // pos-major -> channel-major
            for (int o = og; o < 128; o += 2)
                sw[kl][o] = w[(size_t)o * 2048 + worig];
        }
        __syncthreads();
        for (int kl = 0; kl < 64; kl++) {
            float wv = sw[kl][tid];
#pragma unroll
            for (int r = 0; r < 16; r++) acc[r] += sf[r][kl] * wv;
        }
    }
    for (int r = 0; r < 16; r++)
        g_hid[(size_t)(b0 + r) * 128 + tid] = fmaxf(acc[r] + bias[tid], 0.f);
}

__global__ void k_cls2(const float* __restrict__ w, const float* __restrict__ b,
                       float* __restrict__ out) {
    int bi = blockIdx.x * blockDim.x + threadIdx.x;
    if (bi >= BATCH) return;
    float a0 = b[0], a1 = b[1];
    for (int k = 0; k < 128; k++) {
        float h = g_hid[(size_t)bi * 128 + k];
        a0 += h * w[k];
        a1 += h * w[128 + k];
    }
    out[bi * 2 + 0] = a0;
    out[bi * 2 + 1] = a1;
}

// ---------------- launch ----------------

extern "C" void kernel_launch(void* const* d_in, const int* in_sizes, int n_in,
                              void* d_out, int out_size) {
    const float* x        = (const float*)d_in[0];
    const float* conv1d_w = (const float*)d_in[1];
    const float* conv1d_b = (const float*)d_in[2];
    const float* bn_gamma = (const float*)d_in[3];
    const float* bn_beta  = (const float*)d_in[4];
    const float* bn_mean  = (const float*)d_in[5];
    const float* bn_var   = (const float*)d_in[6];
    const float* lin_w    = (const float*)d_in[7];
    const float* lin_b    = (const float*)d_in[8];
    const float* cell_w   = (const float*)d_in[9];
    const float* cell_b   = (const float*)d_in[10];
    const float* cls1_w   = (const float*)d_in[11];
    const float* cls1_b   = (const float*)d_in[12];
    const float* cls2_w   = (const float*)d_in[13];
    const float* cls2_b   = (const float*)d_in[14];
    float* out = (float*)d_out;

    k_prep_w1<<<(FEAT * 64 + 255) / 256, 256>>>(conv1d_w, conv1d_b, bn_gamma, bn_beta, bn_mean, bn_var);
    k_S<<<(1024 * 64 + 255) / 256, 256>>>(lin_w);
    k_buildQF<<<(2 * 16 * 4 * 2048 + 255) / 256, 256>>>(cell_w);
    k_biasIF<<<(4096 + 255) / 256, 256>>>(cell_w, cell_b, lin_b);
    k_buildWF<<<(9 * 8 * 2048 + 255) / 256, 256>>>(cell_w);
    k_bias_og<<<(2048 + 255) / 256, 256>>>(cell_b);
    k_enc<<<BT / 32, 256>>>(x);
    k_zero<<<(int)(((size_t)BATCH * 2048 + 255) / 256), 256>>>();

    for (int t = 0; t < TSTEPS; t++)
        k_step<<<dim3(BATCH / 64, 16), 256>>>(t);

    k_cls1<<<BATCH / 16, 128>>>(cls1_w, cls1_b);
    k_cls2<<<(BATCH + 127) / 128, 128>>>(cls2_w, cls2_b, out);
}

// round 15
// speedup vs baseline: 2.1348x; 1.0106x over previous
#include <cuda_runtime.h>
#include <math.h>
#include <cstdint>

// ---------------------------------------------------------------------------
// FastConvLSTM, position-major block-sparse recurrence on tf32 mma.sync:
//   h/c layout: [b][pos*128 + ch]
//   pre_i(p) = enc @ Qi(p);  pre_f(p) = enc @ Qf(p) + sum_q h[q,0:32]@W
//   pre_o(p) = sum_q h[q,32:80]@W;  pre_g(p) = sum_q h[q,80:128]@W
//   c = sig(pre_f)*c + sig(pre_i)*tanh(pre_g); h = sig(pre_o)*tanh(c)
// R14: CTA = 128 threads (4 warps), tile 64 batch x 64 ch (position, half).
// 2 CTAs/SM -> cross-CTA latency hiding of B LDG + syncs.
// B weights fragment-canonical in gmem, LDG.64 double buffered; A via
// ping-pong smem us[2][64][20] (conflict-free fragment LDS).
// ---------------------------------------------------------------------------

#define BATCH 2048
#define TSTEPS 128
#define FEAT 84
#define BT (BATCH * TSTEPS)

__device__ __align__(128) float g_W1[FEAT * 64];
__device__ __align__(128) float g_b1[64];
__device__ __align__(128) float g_S[1024 * 64];        // S[o][c]
__device__ __align__(128) float g_QF[2 * 16 * 4 * 2048];   // frag-canonical Qi/Qf
__device__ __align__(128) float g_WF[9 * 8 * 2048];        // frag-canonical Wblk
__device__ __align__(128) float g_bias_if[4096];       // [gate*2048 + pos*128 + co]
__device__ __align__(128) float g_bias_o[2048];        // [pos*128 + co]
__device__ __align__(128) float g_bias_g[2048];
__device__ __align__(128) float g_enc[(size_t)BT * 64];
__device__ __align__(128) float g_h[2][(size_t)BATCH * 2048];
__device__ __align__(128) float g_c[(size_t)BATCH * 2048];
__device__ __align__(128) float g_hid[(size_t)BATCH * 128];

// ---------------- helpers ----------------

__device__ __forceinline__ float to_tf32(float x) {
    uint32_t u; asm("cvt.rna.tf32.f32 %0, %1;" : "=r"(u) : "f"(x));
    return __uint_as_float(u);
}
__device__ __forceinline__ void mma_tf32(float* d, const uint32_t* a, const uint32_t* b) {
    asm volatile(
        "mma.sync.aligned.m16n8k8.row.col.f32.tf32.tf32.f32 "
        "{%0,%1,%2,%3}, {%4,%5,%6,%7}, {%8,%9}, {%0,%1,%2,%3};\n"
        : "+f"(d[0]), "+f"(d[1]), "+f"(d[2]), "+f"(d[3])
        : "r"(a[0]), "r"(a[1]), "r"(a[2]), "r"(a[3]), "r"(b[0]), "r"(b[1]));
}

// ---------------- weight prep kernels ----------------

__global__ void k_prep_w1(const float* __restrict__ cw, const float* __restrict__ cb,
                          const float* __restrict__ gam, const float* __restrict__ bet,
                          const float* __restrict__ mean, const float* __restrict__ var) {
    int i = blockIdx.x * blockDim.x + threadIdx.x;
    if (i >= FEAT * 64) return;
    int f = i / 64, c = i % 64;
    float s = gam[c] * rsqrtf(var[c] + 1e-5f);
    g_W1[f * 64 + c] = cw[c * (FEAT * 3) + f * 3 + 1] * s;   // center tap only
    if (f == 0) g_b1[c] = (cb[c] - mean[c]) * s + bet[c];
}

__global__ void k_S(const float* __restrict__ lin_w) {
    int idx = blockIdx.x * blockDim.x + threadIdx.x;
    if (idx >= 1024 * 64) return;
    int o = idx >> 6, c = idx & 63;
    float s = 0.f;
#pragma unroll
    for (int j = 0; j < 16; j++) s += lin_w[(size_t)o * 1024 + (c << 4) + j];
    g_S[idx] = s;
}

// Q in fragment-canonical order:
// idx = ((((gate*16+p)*4+kc)*2+kk)*16+nt)*64 + lane*2 + e
// value = Q[c = kc*16+kk*8+tig+4e][co = nt*8+gid]  (tf32-rounded)
__global__ void k_buildQF(const float* __restrict__ cell_w) {
    int idx = blockIdx.x * blockDim.x + threadIdx.x;
    if (idx >= 2 * 16 * 4 * 2048) return;
    int e = idx & 1;
    int lane = (idx >> 1) & 31;
    int nt = (idx >> 6) & 15;
    int kk = (idx >> 10) & 1;
    int kc = (idx >> 11) & 3;
    int p = (idx >> 13) & 15;
    int gate = idx >> 17;
    int gid = lane >> 2, tig = lane & 3;
    int c = kc * 16 + kk * 8 + tig + e * 4;
    int co = nt * 8 + gid;
    int py = p >> 2, px = p & 3;
    int wco = (gate == 0) ? co : 128 + co;
    int nci = (gate == 0) ? 48 : 16;
    float acc = 0.f;
    for (int ci = 0; ci < nci; ci++) {
        int xch = (gate == 0) ? ci : 48 + ci;
        for (int ky = 0; ky < 3; ky++) {
            int qy = py + ky - 1; if (qy < 0 || qy > 3) continue;
            for (int kx = 0; kx < 3; kx++) {
                int qx = px + kx - 1; if (qx < 0 || qx > 3) continue;
                float w = cell_w[(size_t)wco * 432 + ci * 9 + ky * 3 + kx];
                acc += w * g_S[(xch * 16 + qy * 4 + qx) * 64 + c];
            }
        }
    }
    g_QF[idx] = to_tf32(acc);
}

__global__ void k_biasIF(const float* __restrict__ cell_w, const float* __restrict__ cell_b,
                         const float* __restrict__ lin_b) {
    int idx = blockIdx.x * blockDim.x + threadIdx.x;
    if (idx >= 4096) return;
    int gate = idx >> 11;
    int p = (idx >> 7) & 15;
    int co = idx & 127;
    int py = p >> 2, px = p & 3;
    int wco = (gate == 0) ? co : 128 + co;
    int nci = (gate == 0) ? 48 : 16;
    float bacc = 0.f;
    for (int ci = 0; ci < nci; ci++) {
        int xch = (gate == 0) ? ci : 48 + ci;
        for (int ky = 0; ky < 3; ky++) {
            int qy = py + ky - 1; if (qy < 0 || qy > 3) continue;
            for (int kx = 0; kx < 3; kx++) {
                int qx = px + kx - 1; if (qx < 0 || qx > 3) continue;
                float w = cell_w[(size_t)wco * 432 + ci * 9 + ky * 3 + kx];
                bacc += w * lin_b[xch * 16 + qy * 4 + qx];
            }
        }
    }
    g_bias_if[idx] = cell_b[wco] + bacc;
}

// Wblk in fragment-canonical order:
// idx = (((di*8+kc)*2+kk)*16+nt)*64 + lane*2 + e
// value = W[ci = kc*16+kk*8+tig+4e][co = nt*8+gid]
__global__ void k_buildWF(const float* __restrict__ cell_w) {
    int idx = blockIdx.x * blockDim.x + threadIdx.x;
    if (idx >= 9 * 8 * 2048) return;
    int e = idx & 1;
    int lane = (idx >> 1) & 31;
    int nt = (idx >> 6) & 15;
    int kk = (idx >> 10) & 1;
    int kc = (idx >> 11) & 7;
    int di = idx >> 14;
    int gid = lane >> 2, tig = lane & 3;
    int ci = kc * 16 + kk * 8 + tig + e * 4;
    int co = nt * 8 + gid;
    int ky = di / 3, kx = di % 3;
    int wco, ig;
    if (ci < 32)      { wco = 128 + co; ig = 16 + ci; }   // gate f: h ch 0..31
    else if (ci < 80) { wco = 256 + co; ig = ci - 32; }   // gate o
    else              { wco = 384 + co; ig = ci - 80; }   // gate g
    g_WF[idx] = to_tf32(cell_w[(size_t)wco * 432 + ig * 9 + ky * 3 + kx]);
}

__global__ void k_bias_og(const float* __restrict__ cell_b) {
    int idx = blockIdx.x * blockDim.x + threadIdx.x;
    if (idx >= 2048) return;
    int co = idx & 127;
    g_bias_o[idx] = cell_b[256 + co];
    g_bias_g[idx] = cell_b[384 + co];
}

// ---------------- encoder (tf32-rounded output) ----------------

__global__ void k_enc(const float* __restrict__ x) {
    __shared__ float sW[FEAT * 64];
    __shared__ float sb[64];
    __shared__ float sx[32][FEAT];
    int tid = threadIdx.x;
    for (int i = tid; i < FEAT * 64; i += 256) sW[i] = g_W1[i];
    if (tid < 64) sb[tid] = g_b1[tid];
    size_t row0 = (size_t)blockIdx.x * 32;
    for (int i = tid; i < 32 * FEAT; i += 256) {
        int r = i / FEAT, f = i % FEAT;
        sx[r][f] = x[(row0 + r) * FEAT + f];
    }
    __syncthreads();
    int c = tid & 63;
    int rg = tid >> 6;
    for (int rr = 0; rr < 8; rr++) {
        int r = rg * 8 + rr;
        float acc = sb[c];
#pragma unroll 4
        for (int f = 0; f < FEAT; f++) acc += sx[r][f] * sW[f * 64 + c];
        g_enc[(row0 + r) * 64 + c] = to_tf32(fmaxf(acc, 0.f));
    }
}

__global__ void k_zero() {
    size_t i = (size_t)blockIdx.x * blockDim.x + threadIdx.x;
    if (i < (size_t)BATCH * 2048) { g_h[0][i] = 0.f; g_c[i] = 0.f; }
}

// ---------------- recurrent step: tf32 mma.sync, 128-thread CTA ----------------

#define LDB(DST, BASE)                                                          \
    do {                                                                        \
        _Pragma("unroll")                                                       \
        for (int kk_ = 0; kk_ < 2; kk_++)                                       \
            _Pragma("unroll")                                                   \
            for (int nt_ = 0; nt_ < 4; nt_++)                                   \
                DST[kk_][nt_] = *(const float2*)((BASE) +                       \
                    ((kk_ * 16 + ntb + nt_) * 64 + lane * 2));                  \
    } while (0)

#define CPB(DST, SRC)                                                           \
    do {                                                                        \
        _Pragma("unroll")                                                       \
        for (int kk_ = 0; kk_ < 2; kk_++)                                       \
            _Pragma("unroll")                                                   \
            for (int nt_ = 0; nt_ < 4; nt_++) DST[kk_][nt_] = SRC[kk_][nt_];    \
    } while (0)

#define DO_CHUNK(ACC, BARR, ST)                                                 \
    do {                                                                        \
        _Pragma("unroll")                                                       \
        for (int kk_ = 0; kk_ < 2; kk_++) {                                     \
            uint32_t af_[2][4];                                                 \
            _Pragma("unroll")                                                   \
            for (int mt_ = 0; mt_ < 2; mt_++) {                                 \
                int r0_ = m0 + mt_ * 16 + gid;                                  \
                af_[mt_][0] = __float_as_uint(us[ST][r0_][kk_ * 8 + tig]);      \
                af_[mt_][1] = __float_as_uint(us[ST][r0_ + 8][kk_ * 8 + tig]);  \
                af_[mt_][2] = __float_as_uint(us[ST][r0_][kk_ * 8 + tig + 4]);  \
                af_[mt_][3] = __float_as_uint(us[ST][r0_ + 8][kk_ * 8 + tig + 4]); \
            }                                                                   \
            _Pragma("unroll")                                                   \
            for (int nt_ = 0; nt_ < 4; nt_++) {                                 \
                uint32_t bf_[2] = {__float_as_uint(BARR[kk_][nt_].x),           \
                                   __float_as_uint(BARR[kk_][nt_].y)};          \
                mma_tf32(&ACC[(0 * 4 + nt_) * 4], af_[0], bf_);                 \
                mma_tf32(&ACC[(1 * 4 + nt_) * 4], af_[1], bf_);                 \
            }                                                                   \
        }                                                                       \
    } while (0)

__global__ void __launch_bounds__(128, 2) k_step(int t) {
    __shared__ __align__(16) float us[2][64][20];
    const int tid = threadIdx.x;
    const int lane = tid & 31, wid = tid >> 5;
    const int gid = lane >> 2, tig = lane & 3;
    const int warp_m = wid & 1, warp_n = wid >> 1;   // 2m x 2n warps
    const int m0 = warp_m * 32;
    const int bb = blockIdx.x << 6;
    const int p = blockIdx.y >> 1;
    const int half = blockIdx.y & 1;
    const int ntb = half * 8 + warp_n * 4;           // global n-tile base (of 16)
    const int py = p >> 2, px = p & 3;
    const int lb = tid >> 1, lk8 = (tid & 1) << 3;   // A loader: row lb, k offset lk8
    const float* __restrict__ hin = g_h[t & 1];
    float* __restrict__ hout = g_h[(t & 1) ^ 1];
    const float* enc_t = g_enc + ((size_t)bb * TSTEPS + t) * 64;
    const float* hrow = hin + (size_t)bb * 2048;

    float acc_i[32], acc_f[32];
#pragma unroll
    for (int e = 0; e < 32; e++) { acc_i[e] = 0.f; acc_f[e] = 0.f; }

    // ===== enc phase: 4 dual chunks (gate i + gate f x-part) =====
    {
        const float* qI = g_QF + (size_t)(0 * 16 + p) * 8192;
        const float* qF = g_QF + (size_t)(1 * 16 + p) * 8192;
        float2 bc[2][4], bc2[2][4], bn[2][4], bn2[2][4];
        float4 av0 = *(const float4*)(enc_t + (size_t)lb * (TSTEPS * 64) + lk8);
        float4 av1 = *(const float4*)(enc_t + (size_t)lb * (TSTEPS * 64) + lk8 + 4);
        LDB(bc, qI);
        LDB(bc2, qF);
        *(float4*)&us[0][lb][lk8] = av0;
        *(float4*)&us[0][lb][lk8 + 4] = av1;
        __syncthreads();
#pragma unroll 1
        for (int kc = 0; kc < 4; kc++) {
            const int st = kc & 1;
            if (kc < 3) {
                av0 = *(const float4*)(enc_t + (size_t)lb * (TSTEPS * 64) + (kc + 1) * 16 + lk8);
                av1 = *(const float4*)(enc_t + (size_t)lb * (TSTEPS * 64) + (kc + 1) * 16 + lk8 + 4);
                LDB(bn, qI + (kc + 1) * 2048);
                LDB(bn2, qF + (kc + 1) * 2048);
            }
            DO_CHUNK(acc_i, bc, st);
            DO_CHUNK(acc_f, bc2, st);
            if (kc < 3) {
                *(float4*)&us[st ^ 1][lb][lk8] = av0;
                *(float4*)&us[st ^ 1][lb][lk8 + 4] = av1;
                CPB(bc, bn);
                CPB(bc2, bn2);
            }
            __syncthreads();
        }
    }

    // ===== h phase: neighbor blocks, k16 chunks =====
    float acc_o[32], acc_g[32];
#pragma unroll
    for (int e = 0; e < 32; e++) { acc_o[e] = 0.f; acc_g[e] = 0.f; }
    {
        int nq[9], nd[9], nn = 0;
#pragma unroll
        for (int di = 0; di < 9; di++) {
            int qy = py + di / 3 - 1, qx = px + di % 3 - 1;
            if ((unsigned)qy < 4u && (unsigned)qx < 4u) { nq[nn] = qy * 4 + qx; nd[nn] = di; nn++; }
        }
        const int NH = nn * 8;
        float2 bc[2][4], bn[2][4];
        float4 av0 = *(const float4*)(hrow + nq[0] * 128 + (size_t)lb * 2048 + lk8);
        float4 av1 = *(const float4*)(hrow + nq[0] * 128 + (size_t)lb * 2048 + lk8 + 4);
        LDB(bc, g_WF + (size_t)nd[0] * 16384);
        *(float4*)&us[0][lb][lk8] = av0;
        *(float4*)&us[0][lb][lk8 + 4] = av1;
        __syncthreads();
#pragma unroll 1
        for (int ci = 0; ci < NH; ci++) {
            const int st = ci & 1;
            if (ci + 1 < NH) {
                int n2 = (ci + 1) >> 3, kt2 = (ci + 1) & 7;
                av0 = *(const float4*)(hrow + nq[n2] * 128 + (size_t)lb * 2048 + kt2 * 16 + lk8);
                av1 = *(const float4*)(hrow + nq[n2] * 128 + (size_t)lb * 2048 + kt2 * 16 + lk8 + 4);
                LDB(bn, g_WF + (size_t)nd[n2] * 16384 + kt2 * 2048);
            }
            const int kt = ci & 7;
            if (kt < 2)      { DO_CHUNK(acc_f, bc, st); }
            else if (kt < 5) { DO_CHUNK(acc_o, bc, st); }
            else             { DO_CHUNK(acc_g, bc, st); }
            if (ci + 1 < NH) {
                *(float4*)&us[st ^ 1][lb][lk8] = av0;
                *(float4*)&us[st ^ 1][lb][lk8 + 4] = av1;
                CPB(bc, bn);
            }
            __syncthreads();
        }
    }

    // ===== fused LSTM epilogue =====
#pragma unroll
    for (int mt = 0; mt < 2; mt++) {
#pragma unroll
        for (int rh = 0; rh < 2; rh++) {
            int row = bb + m0 + mt * 16 + gid + rh * 8;
            size_t roff = (size_t)row * 2048 + p * 128;
#pragma unroll
            for (int nt = 0; nt < 4; nt++) {
                int col = (ntb + nt) * 8 + tig * 2;
                size_t off = roff + col;
                int jn = p * 128 + col;
                float2 cold = *(const float2*)(g_c + off);
                float cold2[2] = {cold.x, cold.y};
                float cn[2], hn[2];
#pragma unroll
                for (int e = 0; e < 2; e++) {
                    int ai = (mt * 4 + nt) * 4 + rh * 2 + e;
                    float pi2 = acc_i[ai] + g_bias_if[jn + e];
                    float pf = acc_f[ai] + g_bias_if[2048 + jn + e];
                    float po = acc_o[ai] + g_bias_o[jn + e];
                    float pg = acc_g[ai] + g_bias_g[jn + e];
                    float si = 1.f / (1.f + __expf(-pi2));
                    float sf = 1.f / (1.f + __expf(-pf));
                    float so = 1.f / (1.f + __expf(-po));
                    float tg = 2.f / (1.f + __expf(-2.f * pg)) - 1.f;
                    float c2 = sf * cold2[e] + si * tg;
                    cn[e] = c2;
                    float tc = 2.f / (1.f + __expf(-2.f * c2)) - 1.f;
                    hn[e] = to_tf32(so * tc);
                }
                *(float2*)(g_c + off)  = make_float2(cn[0], cn[1]);
                *(float2*)(hout + off) = make_float2(hn[0], hn[1]);
            }
        }
    }
}

// ---------------- classifier ----------------
// h columns are position-major (pos*128+co); original feature index = co*16+pos.

__global__ void k_cls1(const float* __restrict__ w, const float* __restrict__ bias) {
    __shared__ float sf[16][64];
    __shared__ float sw[64][129];
    const float* hptr = g_h[0];
    int tid = threadIdx.x;
    int b0 = blockIdx.x * 16;
    float acc[16];
#pragma unroll
    for (int r = 0; r < 16; r++) acc[r] = 0.f;
    for (int k0 = 0; k0 < 2048; k0 += 64) {
        __syncthreads();
        for (int i = tid; i < 16 * 64; i += 128) {
            int r = i / 64, kl = i % 64;
            sf[r][kl] = hptr[(size_t)(b0 + r) * 2048 + k0 + kl];
        }
        {
            int kl = tid % 64, og = tid / 64;
            int kg = k0 + kl;
            int worig = (kg & 127) * 16 + (kg >> 7);   // pos-major -> channel-major
            for (int o = og; o < 128; o += 2)
                sw[kl][o] = w[(size_t)o * 2048 + worig];
        }
        __syncthreads();
        for (int kl = 0; kl < 64; kl++) {
            float wv = sw[kl][tid];
#pragma unroll
            for (int r = 0; r < 16; r++) acc[r] += sf[r][kl] * wv;
        }
    }
    for (int r = 0; r < 16; r++)
        g_hid[(size_t)(b0 + r) * 128 + tid] = fmaxf(acc[r] + bias[tid], 0.f);
}

__global__ void k_cls2(const float* __restrict__ w, const float* __restrict__ b,
                       float* __restrict__ out) {
    int bi = blockIdx.x * blockDim.x + threadIdx.x;
    if (bi >= BATCH) return;
    float a0 = b[0], a1 = b[1];
    for (int k = 0; k < 128; k++) {
        float h = g_hid[(size_t)bi * 128 + k];
        a0 += h * w[k];
        a1 += h * w[128 + k];
    }
    out[bi * 2 + 0] = a0;
    out[bi * 2 + 1] = a1;
}

// ---------------- launch ----------------

extern "C" void kernel_launch(void* const* d_in, const int* in_sizes, int n_in,
                              void* d_out, int out_size) {
    const float* x        = (const float*)d_in[0];
    const float* conv1d_w = (const float*)d_in[1];
    const float* conv1d_b = (const float*)d_in[2];
    const float* bn_gamma = (const float*)d_in[3];
    const float* bn_beta  = (const float*)d_in[4];
    const float* bn_mean  = (const float*)d_in[5];
    const float* bn_var   = (const float*)d_in[6];
    const float* lin_w    = (const float*)d_in[7];
    const float* lin_b    = (const float*)d_in[8];
    const float* cell_w   = (const float*)d_in[9];
    const float* cell_b   = (const float*)d_in[10];
    const float* cls1_w   = (const float*)d_in[11];
    const float* cls1_b   = (const float*)d_in[12];
    const float* cls2_w   = (const float*)d_in[13];
    const float* cls2_b   = (const float*)d_in[14];
    float* out = (float*)d_out;

    k_prep_w1<<<(FEAT * 64 + 255) / 256, 256>>>(conv1d_w, conv1d_b, bn_gamma, bn_beta, bn_mean, bn_var);
    k_S<<<(1024 * 64 + 255) / 256, 256>>>(lin_w);
    k_buildQF<<<(2 * 16 * 4 * 2048 + 255) / 256, 256>>>(cell_w);
    k_biasIF<<<(4096 + 255) / 256, 256>>>(cell_w, cell_b, lin_b);
    k_buildWF<<<(9 * 8 * 2048 + 255) / 256, 256>>>(cell_w);
    k_bias_og<<<(2048 + 255) / 256, 256>>>(cell_b);
    k_enc<<<BT / 32, 256>>>(x);
    k_zero<<<(int)(((size_t)BATCH * 2048 + 255) / 256), 256>>>();

    for (int t = 0; t < TSTEPS; t++)
        k_step<<<dim3(BATCH / 64, 32), 128>>>(t);

    k_cls1<<<BATCH / 16, 128>>>(cls1_w, cls1_b);
    k_cls2<<<(BATCH + 127) / 128, 128>>>(cls2_w, cls2_b, out);
}